// round 6
// baseline (speedup 1.0000x reference)
#include <cuda_runtime.h>
#include <cuda_bf16.h>

// Zero-initialized at module load; last block resets them at the end of every
// launch, so every run (correctness + each graph replay) starts from zero.
__device__ float    g_sum;
__device__ unsigned g_arrived;
__device__ unsigned g_done;

#define NBLOCKS  148
#define NTHREADS 1024
#define UNROLL   4
#define TILE     (NTHREADS * UNROLL)   // 4096 float4 = 64 KB per tile

__global__ void __launch_bounds__(NTHREADS, 1)
fused_kernel(const float4* __restrict__ in, float4* __restrict__ out, long long n4) {
    // ---- tile-granular contiguous chunk per block ----
    long long ntiles = (n4 + TILE - 1) / TILE;
    long long tpb    = (ntiles + gridDim.x - 1) / gridDim.x;
    long long t0     = (long long)blockIdx.x * tpb;
    long long t1     = t0 + tpb;
    if (t1 > ntiles) t1 = ntiles;

    // ---- phase 1: sum own tiles, ascending, 4x unrolled (MLP=4) ----
    float s = 0.0f;
    for (long long t = t0; t < t1; ++t) {
        long long base = t * TILE + threadIdx.x;
        #pragma unroll
        for (int u = 0; u < UNROLL; ++u) {
            long long i = base + (long long)u * NTHREADS;
            if (i < n4) {
                float4 v = in[i];
                s += (v.x + v.y) + (v.z + v.w);
            }
        }
    }
    #pragma unroll
    for (int o = 16; o > 0; o >>= 1)
        s += __shfl_xor_sync(0xffffffffu, s, o);

    __shared__ float sm[32];
    __shared__ float s_factor;
    int lane = threadIdx.x & 31;
    int warp = threadIdx.x >> 5;
    if (lane == 0) sm[warp] = s;
    __syncthreads();
    if (warp == 0) {
        s = (lane < (NTHREADS >> 5)) ? sm[lane] : 0.0f;
        #pragma unroll
        for (int o = 16; o > 0; o >>= 1)
            s += __shfl_xor_sync(0xffffffffu, s, o);
        if (lane == 0) {
            atomicAdd(&g_sum, s);
            __threadfence();
            atomicAdd(&g_arrived, 1u);
        }
    }

    // ---- grid barrier: wait for all blocks' partials ----
    if (threadIdx.x == 0) {
        volatile unsigned* pa = &g_arrived;
        while (*pa < gridDim.x) { /* all 148 blocks resident: spin is safe */ }
        __threadfence();
        volatile float* ps = &g_sum;
        float S = *ps;
        // S>0: 4^32 = 2^64.  S<0: -2*4^31 = -2^63.  S==0: (-2)^32 = 2^32.
        s_factor = (S > 0.0f) ? 0x1p64f : ((S < 0.0f) ? -0x1p63f : 0x1p32f);
    }
    __syncthreads();
    float f = s_factor;

    // ---- phase 2: same tiles in DESCENDING tile order (MRU-first in L2),
    // ascending + unrolled inside each tile for coalescing and MLP.
    // __ldcs: input line is dead after this read -> evict-first.
    // __stcs: output never needed again -> don't let it displace input. ----
    for (long long t = t1 - 1; t >= t0; --t) {
        long long base = t * TILE + threadIdx.x;
        #pragma unroll
        for (int u = 0; u < UNROLL; ++u) {
            long long i = base + (long long)u * NTHREADS;
            if (i < n4) {
                float4 v = __ldcs(&in[i]);
                v.x *= f; v.y *= f; v.z *= f; v.w *= f;
                __stcs(&out[i], v);
            }
        }
    }

    // ---- epilogue: last block resets globals for the next replay ----
    __syncthreads();
    if (threadIdx.x == 0) {
        __threadfence();
        unsigned d = atomicAdd(&g_done, 1u);
        if (d == gridDim.x - 1) {
            g_sum     = 0.0f;
            g_arrived = 0u;
            g_done    = 0u;
            __threadfence();
        }
    }
}

extern "C" void kernel_launch(void* const* d_in, const int* in_sizes, int n_in,
                              void* d_out, int out_size) {
    const float4* in  = (const float4*)d_in[0];
    float4*       out = (float4*)d_out;
    long long n  = (long long)in_sizes[0];   // 32*1024*1024
    long long n4 = n >> 2;                   // float4 count (n divisible by 4)

    fused_kernel<<<NBLOCKS, NTHREADS>>>(in, out, n4);
}

// round 7
// speedup vs baseline: 1.3506x; 1.3506x over previous
#include <cuda_runtime.h>
#include <cuda_bf16.h>

// Zero-initialized at module load; last block resets them at the end of every
// launch, so every run (correctness + each graph replay) starts from zero.
__device__ float    g_sum;
__device__ unsigned g_arrived;
__device__ unsigned g_done;

#define NBLOCKS  148
#define NTHREADS 1024
#define UNROLL   4
#define TILE     (NTHREADS * UNROLL)   // 4096 float4 = 64 KB per tile

// Speculated outcome: S > 0  =>  factor = 4^32 = 2^64 (exact exponent shift).
#define F_GUESS  0x1p64f

__global__ void __launch_bounds__(NTHREADS, 1)
fused_kernel(const float4* __restrict__ in, float4* __restrict__ out, long long n4) {
    // ---- tile-granular contiguous chunk per block ----
    long long ntiles = (n4 + TILE - 1) / TILE;
    long long tpb    = (ntiles + gridDim.x - 1) / gridDim.x;
    long long t0     = (long long)blockIdx.x * tpb;
    long long t1     = t0 + tpb;
    if (t1 > ntiles) t1 = ntiles;

    // ---- phase 1: sum own tiles AND speculatively write out = in * F_GUESS.
    // If the speculation holds (S>0), phase 2 does nothing and total traffic
    // is the 256 MB minimum (one read + one write). ----
    float s = 0.0f;
    for (long long t = t0; t < t1; ++t) {
        long long base = t * TILE + threadIdx.x;
        #pragma unroll
        for (int u = 0; u < UNROLL; ++u) {
            long long i = base + (long long)u * NTHREADS;
            if (i < n4) {
                float4 v = in[i];
                s += (v.x + v.y) + (v.z + v.w);
                float4 w;
                w.x = v.x * F_GUESS; w.y = v.y * F_GUESS;
                w.z = v.z * F_GUESS; w.w = v.w * F_GUESS;
                out[i] = w;
            }
        }
    }
    #pragma unroll
    for (int o = 16; o > 0; o >>= 1)
        s += __shfl_xor_sync(0xffffffffu, s, o);

    __shared__ float sm[32];
    __shared__ float s_factor;
    int lane = threadIdx.x & 31;
    int warp = threadIdx.x >> 5;
    if (lane == 0) sm[warp] = s;
    __syncthreads();
    if (warp == 0) {
        s = (lane < (NTHREADS >> 5)) ? sm[lane] : 0.0f;
        #pragma unroll
        for (int o = 16; o > 0; o >>= 1)
            s += __shfl_xor_sync(0xffffffffu, s, o);
        if (lane == 0) {
            atomicAdd(&g_sum, s);
            __threadfence();
            atomicAdd(&g_arrived, 1u);
        }
    }

    // ---- grid barrier: wait for all blocks' partials ----
    if (threadIdx.x == 0) {
        volatile unsigned* pa = &g_arrived;
        while (*pa < gridDim.x) { /* all 148 blocks resident: spin is safe */ }
        __threadfence();
        volatile float* ps = &g_sum;
        float S = *ps;
        // S>0: 4^32 = 2^64.  S<0: -2*4^31 = -2^63.  S==0: (-2)^32 = 2^32.
        s_factor = (S > 0.0f) ? 0x1p64f : ((S < 0.0f) ? -0x1p63f : 0x1p32f);
    }
    __syncthreads();
    float f = s_factor;

    // ---- phase 2 (mispredict repair only): rewrite with the correct factor.
    // Tile-descending for L2 MRU reuse of the phase-1 input stream. ----
    if (f != F_GUESS) {
        for (long long t = t1 - 1; t >= t0; --t) {
            long long base = t * TILE + threadIdx.x;
            #pragma unroll
            for (int u = 0; u < UNROLL; ++u) {
                long long i = base + (long long)u * NTHREADS;
                if (i < n4) {
                    float4 v = in[i];
                    v.x *= f; v.y *= f; v.z *= f; v.w *= f;
                    out[i] = v;
                }
            }
        }
    }

    // ---- epilogue: last block resets globals for the next replay ----
    __syncthreads();
    if (threadIdx.x == 0) {
        __threadfence();
        unsigned d = atomicAdd(&g_done, 1u);
        if (d == gridDim.x - 1) {
            g_sum     = 0.0f;
            g_arrived = 0u;
            g_done    = 0u;
            __threadfence();
        }
    }
}

extern "C" void kernel_launch(void* const* d_in, const int* in_sizes, int n_in,
                              void* d_out, int out_size) {
    const float4* in  = (const float4*)d_in[0];
    float4*       out = (float4*)d_out;
    long long n  = (long long)in_sizes[0];   // 32*1024*1024
    long long n4 = n >> 2;                   // float4 count (n divisible by 4)

    fused_kernel<<<NBLOCKS, NTHREADS>>>(in, out, n4);
}

// round 8
// speedup vs baseline: 1.3564x; 1.0043x over previous
#include <cuda_runtime.h>
#include <cuda_bf16.h>

// Zero-initialized at module load; last block resets them at the end of every
// launch, so every run (correctness + each graph replay) starts from zero.
__device__ float    g_sum;
__device__ unsigned g_arrived;
__device__ unsigned g_done;

#define NBLOCKS  148
#define NTHREADS 1024
#define UNROLL   4
#define TILE     (NTHREADS * UNROLL)   // 4096 float4 = 64 KB per tile

// Speculated outcome: S > 0  =>  factor = 4^32 = 2^64 (exact exponent shift).
#define F_GUESS  0x1p64f

__global__ void __launch_bounds__(NTHREADS, 1)
fused_kernel(const float4* __restrict__ in, float4* __restrict__ out, long long n4) {
    long long ftiles = n4 / TILE;            // full tiles (2048 for this shape)
    long long rem0   = ftiles * TILE;        // first remainder element (== n4 here)

    // ---- phase 1: grid-stride over tiles (perfect balance), sum AND
    // speculatively write out = in * F_GUESS. Loads batched first (MLP=4). ----
    float s = 0.0f;
    for (long long t = blockIdx.x; t < ftiles; t += gridDim.x) {
        long long base = t * TILE + threadIdx.x;
        float4 v[UNROLL];
        #pragma unroll
        for (int u = 0; u < UNROLL; ++u)
            v[u] = in[base + (long long)u * NTHREADS];
        #pragma unroll
        for (int u = 0; u < UNROLL; ++u) {
            s += (v[u].x + v[u].y) + (v[u].z + v[u].w);
            float4 w;
            w.x = v[u].x * F_GUESS; w.y = v[u].y * F_GUESS;
            w.z = v[u].z * F_GUESS; w.w = v[u].w * F_GUESS;
            out[base + (long long)u * NTHREADS] = w;
        }
    }
    // remainder (empty for this shape; kept for generality)
    for (long long i = rem0 + (long long)blockIdx.x * NTHREADS + threadIdx.x;
         i < n4; i += (long long)gridDim.x * NTHREADS) {
        float4 v = in[i];
        s += (v.x + v.y) + (v.z + v.w);
        float4 w;
        w.x = v.x * F_GUESS; w.y = v.y * F_GUESS;
        w.z = v.z * F_GUESS; w.w = v.w * F_GUESS;
        out[i] = w;
    }

    #pragma unroll
    for (int o = 16; o > 0; o >>= 1)
        s += __shfl_xor_sync(0xffffffffu, s, o);

    __shared__ float sm[32];
    __shared__ float s_factor;
    int lane = threadIdx.x & 31;
    int warp = threadIdx.x >> 5;
    if (lane == 0) sm[warp] = s;
    __syncthreads();
    if (warp == 0) {
        s = (lane < (NTHREADS >> 5)) ? sm[lane] : 0.0f;
        #pragma unroll
        for (int o = 16; o > 0; o >>= 1)
            s += __shfl_xor_sync(0xffffffffu, s, o);
        if (lane == 0) {
            atomicAdd(&g_sum, s);
            __threadfence();
            atomicAdd(&g_arrived, 1u);
        }
    }

    // ---- grid barrier: wait for all blocks' partials ----
    if (threadIdx.x == 0) {
        volatile unsigned* pa = &g_arrived;
        while (*pa < gridDim.x) { /* all 148 blocks resident: spin is safe */ }
        __threadfence();
        volatile float* ps = &g_sum;
        float S = *ps;
        // S>0: 4^32 = 2^64.  S<0: -2*4^31 = -2^63.  S==0: (-2)^32 = 2^32.
        s_factor = (S > 0.0f) ? 0x1p64f : ((S < 0.0f) ? -0x1p63f : 0x1p32f);
    }
    __syncthreads();
    float f = s_factor;

    // ---- phase 2 (mispredict repair only): rewrite with the correct factor. ----
    if (f != F_GUESS) {
        for (long long t = blockIdx.x; t < ftiles; t += gridDim.x) {
            long long base = t * TILE + threadIdx.x;
            #pragma unroll
            for (int u = 0; u < UNROLL; ++u) {
                long long i = base + (long long)u * NTHREADS;
                float4 v = in[i];
                v.x *= f; v.y *= f; v.z *= f; v.w *= f;
                out[i] = v;
            }
        }
        for (long long i = rem0 + (long long)blockIdx.x * NTHREADS + threadIdx.x;
             i < n4; i += (long long)gridDim.x * NTHREADS) {
            float4 v = in[i];
            v.x *= f; v.y *= f; v.z *= f; v.w *= f;
            out[i] = v;
        }
    }

    // ---- epilogue: last block resets globals for the next replay ----
    __syncthreads();
    if (threadIdx.x == 0) {
        __threadfence();
        unsigned d = atomicAdd(&g_done, 1u);
        if (d == gridDim.x - 1) {
            g_sum     = 0.0f;
            g_arrived = 0u;
            g_done    = 0u;
            __threadfence();
        }
    }
}

extern "C" void kernel_launch(void* const* d_in, const int* in_sizes, int n_in,
                              void* d_out, int out_size) {
    const float4* in  = (const float4*)d_in[0];
    float4*       out = (float4*)d_out;
    long long n  = (long long)in_sizes[0];   // 32*1024*1024
    long long n4 = n >> 2;                   // float4 count (n divisible by 4)

    fused_kernel<<<NBLOCKS, NTHREADS>>>(in, out, n4);
}